// round 1
// baseline (speedup 1.0000x reference)
#include <cuda_runtime.h>
#include <cuda_bf16.h>

#define T_   1024
#define H_   1024
#define E_   16
#define I_   512      // MOE_INTER
#define IS_  1024     // SHARED_INTER
#define GUW_ 2048     // 2*SHARED_INTER

// ---------------- scratch (device globals; no allocs) ----------------
__device__ int   g_counts[E_];
__device__ int   g_tok[E_ * T_];
__device__ float g_wt[E_ * T_];
__device__ float g_h[(size_t)E_ * T_ * I_];    // 32 MB worst case
__device__ float g_hs[(size_t)T_ * IS_];       // 4 MB

// ---------------- router ----------------
__global__ void zero_counts_kernel() {
    if (threadIdx.x < E_) g_counts[threadIdx.x] = 0;
}

__global__ void router_kernel(const float* __restrict__ x,
                              const float* __restrict__ rw) {
    __shared__ float sx[H_];
    __shared__ float slog[E_];
    int t = blockIdx.x;
    for (int i = threadIdx.x; i < H_; i += blockDim.x) sx[i] = x[(size_t)t * H_ + i];
    __syncthreads();

    int e    = threadIdx.x >> 4;   // 16 threads per expert, 16 experts = 256 threads
    int lane = threadIdx.x & 15;
    float s = 0.f;
    const float* w = rw + (size_t)e * H_;
    for (int i = lane; i < H_; i += 16) s += sx[i] * w[i];
    #pragma unroll
    for (int off = 8; off; off >>= 1) s += __shfl_down_sync(0xffffffffu, s, off, 16);
    if (lane == 0) slog[e] = s;
    __syncthreads();

    if (threadIdx.x == 0) {
        float l[E_];
        #pragma unroll
        for (int i = 0; i < E_; i++) l[i] = slog[i];
        int   idx[4]; float lv[4]; bool used[E_];
        #pragma unroll
        for (int i = 0; i < E_; i++) used[i] = false;
        // top-4 of logits == top-4 of softmax probs (monotonic)
        for (int k = 0; k < 4; k++) {
            int bi = -1; float bv = -1e30f;
            for (int i = 0; i < E_; i++)
                if (!used[i] && l[i] > bv) { bv = l[i]; bi = i; }
            used[bi] = true; idx[k] = bi; lv[k] = bv;
        }
        // normalized over the selected 4: full-softmax denominator cancels
        float m = lv[0], ws[4], sum = 0.f;
        for (int k = 0; k < 4; k++) { ws[k] = __expf(lv[k] - m); sum += ws[k]; }
        float inv = 1.f / sum;
        for (int k = 0; k < 4; k++) {
            int pos = atomicAdd(&g_counts[idx[k]], 1);
            g_tok[idx[k] * T_ + pos] = t;
            g_wt[idx[k] * T_ + pos]  = ws[k] * inv;
        }
    }
}

// ---------------- routed expert GEMM1: h = silu(xWg) * (xWu) ----------------
// BM=64, BN=64, BK=16, 256 threads, 4x4 micro-tile
__global__ void gemm1_routed(const float* __restrict__ x,
                             const float* __restrict__ wg,
                             const float* __restrict__ wu) {
    const int BM = 64, BN = 64, BK = 16;
    int e   = blockIdx.z;
    int cnt = g_counts[e];
    int row0 = blockIdx.y * BM;
    if (row0 >= cnt) return;
    int col0 = blockIdx.x * BN;

    __shared__ float As[BK][BM];
    __shared__ float Bg[BK][BN];
    __shared__ float Bu[BK][BN];
    __shared__ int   rows[BM];

    int tid = threadIdx.x;
    if (tid < BM) {
        int r = row0 + tid;
        rows[tid] = (r < cnt) ? g_tok[e * T_ + r] : -1;
    }
    __syncthreads();

    int tx = tid & 15, ty = tid >> 4;
    float accg[4][4] = {}, accu[4][4] = {};

    for (int k0 = 0; k0 < H_; k0 += BK) {
        #pragma unroll
        for (int l = 0; l < 4; l++) {
            int idx = tid + l * 256;
            int r = idx >> 4, kk = idx & 15;
            int tr = rows[r];
            As[kk][r] = (tr >= 0) ? x[(size_t)tr * H_ + k0 + kk] : 0.f;
        }
        #pragma unroll
        for (int l = 0; l < 4; l++) {
            int idx = tid + l * 256;
            int kk = idx >> 6, n = idx & 63;
            size_t off = ((size_t)e * H_ + k0 + kk) * I_ + col0 + n;
            Bg[kk][n] = wg[off];
            Bu[kk][n] = wu[off];
        }
        __syncthreads();
        #pragma unroll
        for (int kk = 0; kk < BK; kk++) {
            float a[4], bg[4], bu[4];
            #pragma unroll
            for (int m = 0; m < 4; m++) a[m] = As[kk][ty * 4 + m];
            #pragma unroll
            for (int n = 0; n < 4; n++) { bg[n] = Bg[kk][tx * 4 + n]; bu[n] = Bu[kk][tx * 4 + n]; }
            #pragma unroll
            for (int m = 0; m < 4; m++)
                #pragma unroll
                for (int n = 0; n < 4; n++) {
                    accg[m][n] = fmaf(a[m], bg[n], accg[m][n]);
                    accu[m][n] = fmaf(a[m], bu[n], accu[m][n]);
                }
        }
        __syncthreads();
    }

    #pragma unroll
    for (int m = 0; m < 4; m++) {
        int r = row0 + ty * 4 + m;
        if (r < cnt) {
            float* hp = &g_h[((size_t)e * T_ + r) * I_ + col0 + tx * 4];
            #pragma unroll
            for (int n = 0; n < 4; n++) {
                float g = accg[m][n];
                hp[n] = (g / (1.f + __expf(-g))) * accu[m][n];
            }
        }
    }
}

// ---------------- routed expert GEMM2: out += w * (h Wdown) ----------------
__global__ void gemm2_routed(const float* __restrict__ wd, float* __restrict__ out) {
    const int BM = 64, BN = 64, BK = 16;
    int e   = blockIdx.z;
    int cnt = g_counts[e];
    int row0 = blockIdx.y * BM;
    if (row0 >= cnt) return;
    int col0 = blockIdx.x * BN;

    __shared__ float As[BK][BM];
    __shared__ float Bs[BK][BN];

    int tid = threadIdx.x, tx = tid & 15, ty = tid >> 4;
    float acc[4][4] = {};

    for (int k0 = 0; k0 < I_; k0 += BK) {
        #pragma unroll
        for (int l = 0; l < 4; l++) {
            int idx = tid + l * 256;
            int r = idx >> 4, kk = idx & 15;
            As[kk][r] = (row0 + r < cnt)
                ? g_h[((size_t)e * T_ + row0 + r) * I_ + k0 + kk] : 0.f;
        }
        #pragma unroll
        for (int l = 0; l < 4; l++) {
            int idx = tid + l * 256;
            int kk = idx >> 6, n = idx & 63;
            Bs[kk][n] = wd[((size_t)e * I_ + k0 + kk) * H_ + col0 + n];
        }
        __syncthreads();
        #pragma unroll
        for (int kk = 0; kk < BK; kk++) {
            float a[4], b[4];
            #pragma unroll
            for (int m = 0; m < 4; m++) a[m] = As[kk][ty * 4 + m];
            #pragma unroll
            for (int n = 0; n < 4; n++) b[n] = Bs[kk][tx * 4 + n];
            #pragma unroll
            for (int m = 0; m < 4; m++)
                #pragma unroll
                for (int n = 0; n < 4; n++) acc[m][n] = fmaf(a[m], b[n], acc[m][n]);
        }
        __syncthreads();
    }

    #pragma unroll
    for (int m = 0; m < 4; m++) {
        int r = row0 + ty * 4 + m;
        if (r < cnt) {
            int   t = g_tok[e * T_ + r];
            float w = g_wt[e * T_ + r];
            float* op = &out[(size_t)t * H_ + col0 + tx * 4];
            #pragma unroll
            for (int n = 0; n < 4; n++) atomicAdd(&op[n], w * acc[m][n]);
        }
    }
}

// ---------------- shared expert GEMM1 (fused SwiGLU) ----------------
__global__ void gemm1_shared(const float* __restrict__ x,
                             const float* __restrict__ wgu) {
    const int BM = 64, BN = 64, BK = 16;
    int row0 = blockIdx.y * BM;
    int col0 = blockIdx.x * BN;

    __shared__ float As[BK][BM];
    __shared__ float Bg[BK][BN];
    __shared__ float Bu[BK][BN];

    int tid = threadIdx.x, tx = tid & 15, ty = tid >> 4;
    float accg[4][4] = {}, accu[4][4] = {};

    for (int k0 = 0; k0 < H_; k0 += BK) {
        #pragma unroll
        for (int l = 0; l < 4; l++) {
            int idx = tid + l * 256;
            int r = idx >> 4, kk = idx & 15;
            As[kk][r] = x[(size_t)(row0 + r) * H_ + k0 + kk];
        }
        #pragma unroll
        for (int l = 0; l < 4; l++) {
            int idx = tid + l * 256;
            int kk = idx >> 6, n = idx & 63;
            size_t off = (size_t)(k0 + kk) * GUW_ + col0 + n;
            Bg[kk][n] = wgu[off];
            Bu[kk][n] = wgu[off + IS_];
        }
        __syncthreads();
        #pragma unroll
        for (int kk = 0; kk < BK; kk++) {
            float a[4], bg[4], bu[4];
            #pragma unroll
            for (int m = 0; m < 4; m++) a[m] = As[kk][ty * 4 + m];
            #pragma unroll
            for (int n = 0; n < 4; n++) { bg[n] = Bg[kk][tx * 4 + n]; bu[n] = Bu[kk][tx * 4 + n]; }
            #pragma unroll
            for (int m = 0; m < 4; m++)
                #pragma unroll
                for (int n = 0; n < 4; n++) {
                    accg[m][n] = fmaf(a[m], bg[n], accg[m][n]);
                    accu[m][n] = fmaf(a[m], bu[n], accu[m][n]);
                }
        }
        __syncthreads();
    }

    #pragma unroll
    for (int m = 0; m < 4; m++) {
        float* hp = &g_hs[(size_t)(row0 + ty * 4 + m) * IS_ + col0 + tx * 4];
        #pragma unroll
        for (int n = 0; n < 4; n++) {
            float g = accg[m][n];
            hp[n] = (g / (1.f + __expf(-g))) * accu[m][n];
        }
    }
}

// ---------------- shared expert GEMM2: out += hs Wsdown ----------------
__global__ void gemm2_shared(const float* __restrict__ wsd, float* __restrict__ out) {
    const int BM = 64, BN = 64, BK = 16;
    int row0 = blockIdx.y * BM;
    int col0 = blockIdx.x * BN;

    __shared__ float As[BK][BM];
    __shared__ float Bs[BK][BN];

    int tid = threadIdx.x, tx = tid & 15, ty = tid >> 4;
    float acc[4][4] = {};

    for (int k0 = 0; k0 < IS_; k0 += BK) {
        #pragma unroll
        for (int l = 0; l < 4; l++) {
            int idx = tid + l * 256;
            int r = idx >> 4, kk = idx & 15;
            As[kk][r] = g_hs[(size_t)(row0 + r) * IS_ + k0 + kk];
        }
        #pragma unroll
        for (int l = 0; l < 4; l++) {
            int idx = tid + l * 256;
            int kk = idx >> 6, n = idx & 63;
            Bs[kk][n] = wsd[(size_t)(k0 + kk) * H_ + col0 + n];
        }
        __syncthreads();
        #pragma unroll
        for (int kk = 0; kk < BK; kk++) {
            float a[4], b[4];
            #pragma unroll
            for (int m = 0; m < 4; m++) a[m] = As[kk][ty * 4 + m];
            #pragma unroll
            for (int n = 0; n < 4; n++) b[n] = Bs[kk][tx * 4 + n];
            #pragma unroll
            for (int m = 0; m < 4; m++)
                #pragma unroll
                for (int n = 0; n < 4; n++) acc[m][n] = fmaf(a[m], b[n], acc[m][n]);
        }
        __syncthreads();
    }

    #pragma unroll
    for (int m = 0; m < 4; m++) {
        float* op = &out[(size_t)(row0 + ty * 4 + m) * H_ + col0 + tx * 4];
        #pragma unroll
        for (int n = 0; n < 4; n++) op[n] += acc[m][n];   // sequential after routed atomics
    }
}

// ---------------- launch ----------------
extern "C" void kernel_launch(void* const* d_in, const int* in_sizes, int n_in,
                              void* d_out, int out_size) {
    const float* x   = (const float*)d_in[0];  // hidden_states [T,H]
    const float* rw  = (const float*)d_in[1];  // router_w [E,H]
    const float* wg  = (const float*)d_in[2];  // w_gate [E,H,I]
    const float* wu  = (const float*)d_in[3];  // w_up   [E,H,I]
    const float* wd  = (const float*)d_in[4];  // w_down [E,I,H]
    const float* wgu = (const float*)d_in[5];  // ws_gate_up [H,2*Is]
    const float* wsd = (const float*)d_in[6];  // ws_down [Is,H]
    float* out = (float*)d_out;

    cudaMemsetAsync(out, 0, (size_t)out_size * sizeof(float), 0);
    zero_counts_kernel<<<1, 32>>>();
    router_kernel<<<T_, 256>>>(x, rw);
    gemm1_routed<<<dim3(I_ / 64, T_ / 64, E_), 256>>>(x, wg, wu);
    gemm2_routed<<<dim3(H_ / 64, T_ / 64, E_), 256>>>(wd, out);
    gemm1_shared<<<dim3(IS_ / 64, T_ / 64), 256>>>(x, wgu);
    gemm2_shared<<<dim3(H_ / 64, T_ / 64), 256>>>(wsd, out);
}

// round 2
// speedup vs baseline: 1.5754x; 1.5754x over previous
#include <cuda_runtime.h>
#include <cuda_bf16.h>
#include <cstdint>

#define T_   1024
#define H_   1024
#define E_   16
#define I_   512      // MOE_INTER
#define IS_  1024     // SHARED_INTER
#define GUW_ 2048     // 2*SHARED_INTER

// ---------------- scratch (device globals; no allocs) ----------------
__device__ int   g_counts[E_];
__device__ int   g_tok[E_ * T_];
__device__ float g_wt[E_ * T_];
__device__ float g_h[(size_t)E_ * T_ * I_];    // routed intermediate (worst case 32 MB)
__device__ float g_hs[(size_t)T_ * IS_];       // shared-expert intermediate (4 MB)

// ---------------- f32x2 helpers (Blackwell paired-FP32 pipe) ----------------
__device__ __forceinline__ unsigned long long dup2(float v) {
    unsigned long long r;
    asm("mov.b64 %0, {%1, %1};" : "=l"(r) : "f"(v));
    return r;
}
__device__ __forceinline__ void fma2(unsigned long long& acc,
                                     unsigned long long a,
                                     unsigned long long b) {
    asm("fma.rn.f32x2 %0, %1, %2, %0;" : "+l"(acc) : "l"(a), "l"(b));
}
__device__ __forceinline__ float2 unpk2(unsigned long long v) {
    float2 f;
    asm("mov.b64 {%0, %1}, %2;" : "=f"(f.x), "=f"(f.y) : "l"(v));
    return f;
}
__device__ __forceinline__ float silu_mul(float g, float u) {
    return (g / (1.f + __expf(-g))) * u;
}

// ---------------- router ----------------
__global__ void zero_counts_kernel() {
    if (threadIdx.x < E_) g_counts[threadIdx.x] = 0;
}

__global__ void router_kernel(const float* __restrict__ x,
                              const float* __restrict__ rw) {
    __shared__ float sx[H_];
    __shared__ float slog[E_];
    int t = blockIdx.x;
    for (int i = threadIdx.x; i < H_; i += blockDim.x) sx[i] = x[(size_t)t * H_ + i];
    __syncthreads();

    int e    = threadIdx.x >> 4;   // 16 threads per expert
    int lane = threadIdx.x & 15;
    float s = 0.f;
    const float* w = rw + (size_t)e * H_;
    for (int i = lane; i < H_; i += 16) s += sx[i] * w[i];
    #pragma unroll
    for (int off = 8; off; off >>= 1) s += __shfl_down_sync(0xffffffffu, s, off, 16);
    if (lane == 0) slog[e] = s;
    __syncthreads();

    if (threadIdx.x == 0) {
        float l[E_];
        #pragma unroll
        for (int i = 0; i < E_; i++) l[i] = slog[i];
        int idx[4]; float lv[4]; bool used[E_];
        #pragma unroll
        for (int i = 0; i < E_; i++) used[i] = false;
        for (int k = 0; k < 4; k++) {     // top-4 of logits == top-4 of probs
            int bi = -1; float bv = -1e30f;
            for (int i = 0; i < E_; i++)
                if (!used[i] && l[i] > bv) { bv = l[i]; bi = i; }
            used[bi] = true; idx[k] = bi; lv[k] = bv;
        }
        float m = lv[0], ws[4], sum = 0.f;   // softmax denom cancels under top-k norm
        for (int k = 0; k < 4; k++) { ws[k] = __expf(lv[k] - m); sum += ws[k]; }
        float inv = 1.f / sum;
        for (int k = 0; k < 4; k++) {
            int pos = atomicAdd(&g_counts[idx[k]], 1);
            g_tok[idx[k] * T_ + pos] = t;
            g_wt[idx[k] * T_ + pos]  = ws[k] * inv;
        }
    }
}

// =====================================================================
// Unified GEMM1: h = silu(A Wg) * (A Wu)
//   z==0 : shared expert (all tokens, Bg/Bu interleaved in ws_gate_up, ncol=IS_)
//   z>0  : routed expert e=z-1 (gathered token rows, ncol=I_)
// BM=128, BN=64, BK=16, 256 threads, micro 8x4, f32x2 (paired along M)
// =====================================================================
__global__ __launch_bounds__(256, 2)
void gemm1_unified(const float* __restrict__ x,
                   const float* __restrict__ wg,
                   const float* __restrict__ wu,
                   const float* __restrict__ wgu) {
    const int BM = 128, BN = 64, BK = 16;
    int z = blockIdx.z;
    int col0 = blockIdx.x * BN;
    int row0 = blockIdx.y * BM;

    int cnt, e;
    const float *Bgp, *Bup;
    long ldb;
    float* hout;
    long ldo;
    if (z == 0) {                       // shared expert
        e = -1; cnt = T_;
        Bgp = wgu + col0; Bup = wgu + IS_ + col0; ldb = GUW_;
        hout = g_hs; ldo = IS_;
    } else {
        e = z - 1; cnt = g_counts[e];
        if (col0 >= I_) return;
        if (row0 >= cnt) return;
        size_t wo = (size_t)e * H_ * I_ + col0;
        Bgp = wg + wo; Bup = wu + wo; ldb = I_;
        hout = g_h + (size_t)e * T_ * I_; ldo = I_;
    }
    if (row0 >= cnt) return;

    __shared__ float As[BK][132];       // padded, 16B-aligned slices
    __shared__ float Bg[BK][BN];
    __shared__ float Bu[BK][BN];
    __shared__ int   rows[BM];

    int tid = threadIdx.x;
    if (tid < BM) {
        int r = row0 + tid;
        rows[tid] = (z == 0) ? r : ((r < cnt) ? g_tok[e * T_ + r] : -1);
    }
    __syncthreads();

    int tx = tid & 15;                  // col group: cols tx*4..tx*4+3
    int ty = tid >> 4;                  // row group: rows ty*8..ty*8+7

    unsigned long long accg[4][4] = {}, accu[4][4] = {};

    int ar  = tid >> 2;                 // A-load: 2 rows per thread
    int ak  = (tid & 3) * 4;
    int bkk = tid >> 4;                 // B-load: 1 float4 per thread
    int bn  = (tid & 15) * 4;

    for (int k0 = 0; k0 < H_; k0 += BK) {
        // load A (gathered, transposed to k-major)
        #pragma unroll
        for (int h = 0; h < 2; h++) {
            int r = ar + h * 64;
            int tr = rows[r];
            float4 v = (tr >= 0) ? *(const float4*)&x[(size_t)tr * H_ + k0 + ak]
                                 : make_float4(0.f, 0.f, 0.f, 0.f);
            As[ak + 0][r] = v.x; As[ak + 1][r] = v.y;
            As[ak + 2][r] = v.z; As[ak + 3][r] = v.w;
        }
        // load Bg/Bu
        {
            long bo = (long)(k0 + bkk) * ldb + bn;
            *(float4*)&Bg[bkk][bn] = *(const float4*)&Bgp[bo];
            *(float4*)&Bu[bkk][bn] = *(const float4*)&Bup[bo];
        }
        __syncthreads();

        #pragma unroll
        for (int kk = 0; kk < BK; kk++) {
            ulonglong2 a01 = *(const ulonglong2*)&As[kk][ty * 8];
            ulonglong2 a23 = *(const ulonglong2*)&As[kk][ty * 8 + 4];
            unsigned long long a2[4] = {a01.x, a01.y, a23.x, a23.y};
            float4 gv = *(const float4*)&Bg[kk][tx * 4];
            float4 uv = *(const float4*)&Bu[kk][tx * 4];
            unsigned long long g2[4] = {dup2(gv.x), dup2(gv.y), dup2(gv.z), dup2(gv.w)};
            unsigned long long u2[4] = {dup2(uv.x), dup2(uv.y), dup2(uv.z), dup2(uv.w)};
            #pragma unroll
            for (int m = 0; m < 4; m++)
                #pragma unroll
                for (int n = 0; n < 4; n++) {
                    fma2(accg[m][n], a2[m], g2[n]);
                    fma2(accu[m][n], a2[m], u2[n]);
                }
        }
        __syncthreads();
    }

    // epilogue: silu(g)*u, vectorized store
    #pragma unroll
    for (int m = 0; m < 4; m++) {
        float2 gA[4], uA[4];
        #pragma unroll
        for (int n = 0; n < 4; n++) { gA[n] = unpk2(accg[m][n]); uA[n] = unpk2(accu[m][n]); }
        #pragma unroll
        for (int h = 0; h < 2; h++) {
            int lr = ty * 8 + 2 * m + h;
            int r = row0 + lr;
            if (r < cnt) {
                float4 o;
                o.x = silu_mul(h ? gA[0].y : gA[0].x, h ? uA[0].y : uA[0].x);
                o.y = silu_mul(h ? gA[1].y : gA[1].x, h ? uA[1].y : uA[1].x);
                o.z = silu_mul(h ? gA[2].y : gA[2].x, h ? uA[2].y : uA[2].x);
                o.w = silu_mul(h ? gA[3].y : gA[3].x, h ? uA[3].y : uA[3].x);
                *(float4*)&hout[(size_t)r * ldo + col0 + tx * 4] = o;
            }
        }
    }
}

// =====================================================================
// Unified GEMM2: out += w * (h Wdown)
//   z==0 : shared expert (A=g_hs, K=IS_, B=ws_down, w=1)
//   z>0  : routed e=z-1  (A=g_h slab, K=I_, B=w_down, w=g_wt)
// BM=128, BN=128, BK=16, 256 threads, micro 8x8, f32x2, atomicAdd epilogue
// =====================================================================
__global__ __launch_bounds__(256, 2)
void gemm2_unified(const float* __restrict__ wd,
                   const float* __restrict__ wsd,
                   float* __restrict__ out) {
    const int BM = 128, BN = 128, BK = 16;
    int z = blockIdx.z;
    int col0 = blockIdx.x * BN;
    int row0 = blockIdx.y * BM;

    int cnt, e, K;
    const float *Ap, *Bp;
    long lda;
    if (z == 0) {
        e = -1; cnt = T_; K = IS_;
        Ap = g_hs; lda = IS_;
        Bp = wsd + col0;
    } else {
        e = z - 1; cnt = g_counts[e]; K = I_;
        if (row0 >= cnt) return;
        Ap = g_h + (size_t)e * T_ * I_; lda = I_;
        Bp = wd + (size_t)e * I_ * H_ + col0;
    }
    if (row0 >= cnt) return;

    __shared__ float As[BK][132];
    __shared__ float Bs[BK][BN];

    int tid = threadIdx.x;
    int tx = tid & 15;                  // cols tx*8..tx*8+7
    int ty = tid >> 4;                  // rows ty*8..ty*8+7

    unsigned long long acc[4][8] = {};

    int ar  = tid >> 2;                 // A-load rows
    int ak  = (tid & 3) * 4;
    int bkk = tid >> 5;                 // B-load: 2 float4 per thread
    int bn  = (tid & 31) * 4;

    for (int k0 = 0; k0 < K; k0 += BK) {
        #pragma unroll
        for (int h = 0; h < 2; h++) {
            int r = ar + h * 64;
            float4 v = (row0 + r < cnt)
                ? *(const float4*)&Ap[(size_t)(row0 + r) * lda + k0 + ak]
                : make_float4(0.f, 0.f, 0.f, 0.f);
            As[ak + 0][r] = v.x; As[ak + 1][r] = v.y;
            As[ak + 2][r] = v.z; As[ak + 3][r] = v.w;
        }
        #pragma unroll
        for (int h = 0; h < 2; h++) {
            int kk = bkk + h * 8;
            *(float4*)&Bs[kk][bn] = *(const float4*)&Bp[(size_t)(k0 + kk) * H_ + bn];
        }
        __syncthreads();

        #pragma unroll
        for (int kk = 0; kk < BK; kk++) {
            ulonglong2 a01 = *(const ulonglong2*)&As[kk][ty * 8];
            ulonglong2 a23 = *(const ulonglong2*)&As[kk][ty * 8 + 4];
            unsigned long long a2[4] = {a01.x, a01.y, a23.x, a23.y};
            float4 b0 = *(const float4*)&Bs[kk][tx * 8];
            float4 b1 = *(const float4*)&Bs[kk][tx * 8 + 4];
            unsigned long long b2[8] = {dup2(b0.x), dup2(b0.y), dup2(b0.z), dup2(b0.w),
                                        dup2(b1.x), dup2(b1.y), dup2(b1.z), dup2(b1.w)};
            #pragma unroll
            for (int m = 0; m < 4; m++)
                #pragma unroll
                for (int n = 0; n < 8; n++)
                    fma2(acc[m][n], a2[m], b2[n]);
        }
        __syncthreads();
    }

    // epilogue: weighted atomic accumulate into out
    #pragma unroll
    for (int m = 0; m < 4; m++) {
        float2 v[8];
        #pragma unroll
        for (int n = 0; n < 8; n++) v[n] = unpk2(acc[m][n]);
        #pragma unroll
        for (int h = 0; h < 2; h++) {
            int lr = ty * 8 + 2 * m + h;
            int r = row0 + lr;
            if (r < cnt) {
                int   t = (z == 0) ? r : g_tok[e * T_ + r];
                float w = (z == 0) ? 1.f : g_wt[e * T_ + r];
                float* op = &out[(size_t)t * H_ + col0 + tx * 8];
                #pragma unroll
                for (int n = 0; n < 8; n++)
                    atomicAdd(&op[n], w * (h ? v[n].y : v[n].x));
            }
        }
    }
}

// ---------------- launch ----------------
extern "C" void kernel_launch(void* const* d_in, const int* in_sizes, int n_in,
                              void* d_out, int out_size) {
    const float* x   = (const float*)d_in[0];  // hidden_states [T,H]
    const float* rw  = (const float*)d_in[1];  // router_w [E,H]
    const float* wg  = (const float*)d_in[2];  // w_gate [E,H,I]
    const float* wu  = (const float*)d_in[3];  // w_up   [E,H,I]
    const float* wd  = (const float*)d_in[4];  // w_down [E,I,H]
    const float* wgu = (const float*)d_in[5];  // ws_gate_up [H,2*Is]
    const float* wsd = (const float*)d_in[6];  // ws_down [Is,H]
    float* out = (float*)d_out;

    cudaMemsetAsync(out, 0, (size_t)out_size * sizeof(float), 0);
    zero_counts_kernel<<<1, 32>>>();
    router_kernel<<<T_, 256>>>(x, rw);
    // z=0 is the shared expert (2x K work in gemm2) -> scheduled first
    gemm1_unified<<<dim3(IS_ / 64, T_ / 128, E_ + 1), 256>>>(x, wg, wu, wgu);
    gemm2_unified<<<dim3(H_ / 128, T_ / 128, E_ + 1), 256>>>(wd, wsd, out);
}

// round 4
// speedup vs baseline: 2.4510x; 1.5558x over previous
#include <cuda_runtime.h>
#include <cuda_bf16.h>
#include <cstdint>

#define T_   1024
#define H_   1024
#define E_   16
#define I_   512      // MOE_INTER
#define IS_  1024     // SHARED_INTER
#define GUW_ 2048     // 2*SHARED_INTER

// ---------------- scratch (device globals; no allocs) ----------------
__device__ int   g_counts[E_];
__device__ int   g_tok[E_ * T_];
__device__ float g_wt[E_ * T_];
__device__ float g_h[(size_t)E_ * T_ * I_];    // routed intermediate
__device__ float g_hs[(size_t)T_ * IS_];       // shared-expert intermediate

// ---------------- helpers ----------------
__device__ __forceinline__ uint32_t tf32r(float f) {   // round-to-nearest tf32
    uint32_t r;
    asm("cvt.rna.tf32.f32 %0, %1;" : "=r"(r) : "f"(f));
    return r;
}
__device__ __forceinline__ float silu_mul(float g, float u) {
    return (g / (1.f + __expf(-g))) * u;
}
// m16n8k8 tf32 MMA, D += A*B (A row-major, B col-major/n-major)
__device__ __forceinline__ void mma8(float* d, const uint32_t* a, const uint32_t* b) {
    asm volatile(
        "mma.sync.aligned.m16n8k8.row.col.f32.tf32.tf32.f32 "
        "{%0,%1,%2,%3}, {%4,%5,%6,%7}, {%8,%9}, {%0,%1,%2,%3};"
        : "+f"(d[0]), "+f"(d[1]), "+f"(d[2]), "+f"(d[3])
        : "r"(a[0]), "r"(a[1]), "r"(a[2]), "r"(a[3]), "r"(b[0]), "r"(b[1]));
}

#define SA 36                  // smem row stride in floats (conflict-free, 144B-aligned)
#define A_SZ  (128 * SA)       // A stage: 128 rows x 32 k
#define B64_SZ (64 * SA)       // 64-row B stage
#define B128_SZ (128 * SA)     // 128-row B stage

// ---------------- router ----------------
__global__ void zero_counts_kernel() {
    if (threadIdx.x < E_) g_counts[threadIdx.x] = 0;
}

__global__ void router_kernel(const float* __restrict__ x,
                              const float* __restrict__ rw) {
    __shared__ float sx[H_];
    __shared__ float slog[E_];
    int t = blockIdx.x;
    for (int i = threadIdx.x; i < H_; i += blockDim.x) sx[i] = x[(size_t)t * H_ + i];
    __syncthreads();
    int e = threadIdx.x >> 4, lane = threadIdx.x & 15;
    float s = 0.f;
    const float* w = rw + (size_t)e * H_;
    for (int i = lane; i < H_; i += 16) s += sx[i] * w[i];
    #pragma unroll
    for (int off = 8; off; off >>= 1) s += __shfl_down_sync(0xffffffffu, s, off, 16);
    if (lane == 0) slog[e] = s;
    __syncthreads();
    if (threadIdx.x == 0) {
        float l[E_];
        #pragma unroll
        for (int i = 0; i < E_; i++) l[i] = slog[i];
        int idx[4]; float lv[4]; bool used[E_];
        #pragma unroll
        for (int i = 0; i < E_; i++) used[i] = false;
        for (int k = 0; k < 4; k++) {      // top-4 of logits == top-4 of probs
            int bi = -1; float bv = -1e30f;
            for (int i = 0; i < E_; i++)
                if (!used[i] && l[i] > bv) { bv = l[i]; bi = i; }
            used[bi] = true; idx[k] = bi; lv[k] = bv;
        }
        float m = lv[0], ws[4], sum = 0.f;  // softmax denom cancels under top-k norm
        for (int k = 0; k < 4; k++) { ws[k] = __expf(lv[k] - m); sum += ws[k]; }
        float inv = 1.f / sum;
        for (int k = 0; k < 4; k++) {
            int pos = atomicAdd(&g_counts[idx[k]], 1);
            g_tok[idx[k] * T_ + pos] = t;
            g_wt[idx[k] * T_ + pos]  = ws[k] * inv;
        }
    }
}

// =====================================================================
// GEMM1 (tf32 mma.sync): h = silu(A Wg) * (A Wu)
// BM=128, BN=64 (dual g/u), BK=32, 256 threads (8 warps, warp tile 32x32x2)
// z==0: shared expert; z>0: routed expert z-1 (gathered rows)
// =====================================================================
__global__ __launch_bounds__(256)
void gemm1_mma(const float* __restrict__ x,
               const float* __restrict__ wg,
               const float* __restrict__ wu,
               const float* __restrict__ wgu) {
    extern __shared__ float sm[];
    float* As = sm;                   // [2][A_SZ]
    float* Bg = sm + 2 * A_SZ;        // [2][B64_SZ]
    float* Bu = Bg + 2 * B64_SZ;      // [2][B64_SZ]
    int* rows_s = (int*)(Bu + 2 * B64_SZ);

    int z = blockIdx.z, cx = blockIdx.x, row0 = blockIdx.y * 128;
    int cnt, e; const float *Bgp, *Bup; long ldb; float* hout; int ldo;
    if (z == 0) {
        e = -1; cnt = T_;
        int c0 = cx * 64;
        Bgp = wgu + c0; Bup = wgu + IS_ + c0; ldb = GUW_;
        hout = g_hs + c0; ldo = IS_;
    } else {
        e = z - 1;
        if (cx >= I_ / 64) return;
        cnt = g_counts[e];
        if (row0 >= cnt) return;
        int c0 = cx * 64;
        size_t wo = (size_t)e * H_ * I_ + c0;
        Bgp = wg + wo; Bup = wu + wo; ldb = I_;
        hout = g_h + (size_t)e * T_ * I_ + c0; ldo = I_;
    }
    if (row0 >= cnt) return;

    int tid = threadIdx.x;
    if (tid < 128) {
        int r = row0 + tid;
        rows_s[tid] = (z == 0) ? r : ((r < cnt) ? g_tok[e * T_ + r] : -1);
    }
    __syncthreads();

    // loader roles
    int arow = tid & 127, akc = (tid >> 7) * 16;       // A: row, 16 k per thread
    int tr = rows_s[arow];
    const float* agf = x + (size_t)(tr < 0 ? 0 : tr) * H_ + akc;
    int bkk = tid & 31, bgrp = tid >> 5;               // B: k-row, n-group
    int bn0 = (bgrp & 3) * 16;
    const float* bbase = ((bgrp < 4) ? Bgp : Bup) + (size_t)bkk * ldb + bn0;
    float* bsm = (bgrp < 4) ? Bg : Bu;

    int lane = tid & 31, wid = tid >> 5, gid = lane >> 2, t4 = lane & 3;
    int wm = wid & 3, wn = wid >> 2;

    float accg[2][4][4] = {}, accu[2][4][4] = {};
    float4 pa[4], pb[4];
    #pragma unroll
    for (int j = 0; j < 4; j++) pa[j] = (tr >= 0) ? *(const float4*)(agf + j * 4)
                                                  : make_float4(0.f, 0.f, 0.f, 0.f);
    #pragma unroll
    for (int j = 0; j < 4; j++) pb[j] = *(const float4*)(bbase + j * 4);

    const int NIT = H_ / 32;
    for (int it = 0; it < NIT; ++it) {
        int s = it & 1;
        // ---- STS (cvt to tf32)
        {
            float* a = As + s * A_SZ;
            #pragma unroll
            for (int j = 0; j < 4; j++) {
                float4 v = pa[j], w;
                w.x = __uint_as_float(tf32r(v.x)); w.y = __uint_as_float(tf32r(v.y));
                w.z = __uint_as_float(tf32r(v.z)); w.w = __uint_as_float(tf32r(v.w));
                *(float4*)(a + arow * SA + akc + j * 4) = w;
            }
            uint32_t* b = (uint32_t*)(bsm + s * B64_SZ);
            #pragma unroll
            for (int j = 0; j < 4; j++) {
                float4 v = pb[j]; int n = bn0 + j * 4;
                b[(n + 0) * SA + bkk] = tf32r(v.x);
                b[(n + 1) * SA + bkk] = tf32r(v.y);
                b[(n + 2) * SA + bkk] = tf32r(v.z);
                b[(n + 3) * SA + bkk] = tf32r(v.w);
            }
        }
        __syncthreads();
        // ---- prefetch next tile (overlaps mma phase)
        if (it + 1 < NIT) {
            const float* ap = agf + (it + 1) * 32;
            #pragma unroll
            for (int j = 0; j < 4; j++) pa[j] = (tr >= 0) ? *(const float4*)(ap + j * 4)
                                                          : make_float4(0.f, 0.f, 0.f, 0.f);
            const float* bp = bbase + (size_t)(it + 1) * 32 * ldb;
            #pragma unroll
            for (int j = 0; j < 4; j++) pb[j] = *(const float4*)(bp + j * 4);
        }
        // ---- mma phase
        {
            const uint32_t* a  = (const uint32_t*)(As + s * A_SZ);
            const uint32_t* bg = (const uint32_t*)(Bg + s * B64_SZ);
            const uint32_t* bu = (const uint32_t*)(Bu + s * B64_SZ);
            #pragma unroll
            for (int kb = 0; kb < 32; kb += 8) {
                uint32_t af[2][4];
                #pragma unroll
                for (int mi = 0; mi < 2; mi++) {
                    int r = wm * 32 + mi * 16 + gid;
                    af[mi][0] = a[r * SA + kb + t4];
                    af[mi][1] = a[(r + 8) * SA + kb + t4];
                    af[mi][2] = a[r * SA + kb + t4 + 4];
                    af[mi][3] = a[(r + 8) * SA + kb + t4 + 4];
                }
                #pragma unroll
                for (int ni = 0; ni < 4; ni++) {
                    int n = wn * 32 + ni * 8 + gid;
                    uint32_t bfg[2] = {bg[n * SA + kb + t4], bg[n * SA + kb + t4 + 4]};
                    uint32_t bfu[2] = {bu[n * SA + kb + t4], bu[n * SA + kb + t4 + 4]};
                    #pragma unroll
                    for (int mi = 0; mi < 2; mi++) {
                        mma8(accg[mi][ni], af[mi], bfg);
                        mma8(accu[mi][ni], af[mi], bfu);
                    }
                }
            }
        }
        __syncthreads();
    }

    // ---- epilogue: silu(g)*u, float2 stores
    #pragma unroll
    for (int mi = 0; mi < 2; mi++) {
        #pragma unroll
        for (int ni = 0; ni < 4; ni++) {
            int rb = row0 + wm * 32 + mi * 16 + gid;
            int c  = wn * 32 + ni * 8 + t4 * 2;
            if (rb < cnt) {
                float2 o;
                o.x = silu_mul(accg[mi][ni][0], accu[mi][ni][0]);
                o.y = silu_mul(accg[mi][ni][1], accu[mi][ni][1]);
                *(float2*)(hout + (size_t)rb * ldo + c) = o;
            }
            if (rb + 8 < cnt) {
                float2 o;
                o.x = silu_mul(accg[mi][ni][2], accu[mi][ni][2]);
                o.y = silu_mul(accg[mi][ni][3], accu[mi][ni][3]);
                *(float2*)(hout + (size_t)(rb + 8) * ldo + c) = o;
            }
        }
    }
}

// =====================================================================
// GEMM2 (tf32 mma.sync): out += w * (h Wdown)
// BM=128, BN=128, BK=32, 256 threads (8 warps, warp tile 32x64)
// =====================================================================
__global__ __launch_bounds__(256)
void gemm2_mma(const float* __restrict__ wd,
               const float* __restrict__ wsd,
               float* __restrict__ out) {
    extern __shared__ float sm[];
    float* As = sm;                   // [2][A_SZ]
    float* Bs = sm + 2 * A_SZ;        // [2][B128_SZ]

    int z = blockIdx.z, col0 = blockIdx.x * 128, row0 = blockIdx.y * 128;
    int cnt, e, K; const float *Ap, *Bp; long lda;
    if (z == 0) {
        e = -1; cnt = T_; K = IS_;
        Ap = g_hs; lda = IS_;
        Bp = wsd + col0;
    } else {
        e = z - 1; cnt = g_counts[e]; K = I_;
        if (row0 >= cnt) return;
        Ap = g_h + (size_t)e * T_ * I_; lda = I_;
        Bp = wd + (size_t)e * I_ * H_ + col0;
    }
    if (row0 >= cnt) return;

    int tid = threadIdx.x;
    int arow = tid & 127, akc = (tid >> 7) * 16;
    int ar = row0 + arow;
    bool aok = (ar < cnt);
    const float* agf = Ap + (size_t)ar * lda + akc;
    int bkk = tid & 31, bn0 = (tid >> 5) * 16;
    const float* bbase = Bp + (size_t)bkk * H_ + bn0;

    int lane = tid & 31, wid = tid >> 5, gid = lane >> 2, t4 = lane & 3;
    int wm = wid & 3, wn = wid >> 2;

    float acc[2][8][4] = {};
    float4 pa[4], pb[4];
    #pragma unroll
    for (int j = 0; j < 4; j++) pa[j] = aok ? *(const float4*)(agf + j * 4)
                                            : make_float4(0.f, 0.f, 0.f, 0.f);
    #pragma unroll
    for (int j = 0; j < 4; j++) pb[j] = *(const float4*)(bbase + j * 4);

    const int NIT = K / 32;
    for (int it = 0; it < NIT; ++it) {
        int s = it & 1;
        {
            float* a = As + s * A_SZ;
            #pragma unroll
            for (int j = 0; j < 4; j++) {
                float4 v = pa[j], w;
                w.x = __uint_as_float(tf32r(v.x)); w.y = __uint_as_float(tf32r(v.y));
                w.z = __uint_as_float(tf32r(v.z)); w.w = __uint_as_float(tf32r(v.w));
                *(float4*)(a + arow * SA + akc + j * 4) = w;
            }
            uint32_t* b = (uint32_t*)(Bs + s * B128_SZ);
            #pragma unroll
            for (int j = 0; j < 4; j++) {
                float4 v = pb[j]; int n = bn0 + j * 4;
                b[(n + 0) * SA + bkk] = tf32r(v.x);
                b[(n + 1) * SA + bkk] = tf32r(v.y);
                b[(n + 2) * SA + bkk] = tf32r(v.z);
                b[(n + 3) * SA + bkk] = tf32r(v.w);
            }
        }
        __syncthreads();
        if (it + 1 < NIT) {
            const float* ap = agf + (it + 1) * 32;
            #pragma unroll
            for (int j = 0; j < 4; j++) pa[j] = aok ? *(const float4*)(ap + j * 4)
                                                    : make_float4(0.f, 0.f, 0.f, 0.f);
            const float* bp = bbase + (size_t)(it + 1) * 32 * H_;
            #pragma unroll
            for (int j = 0; j < 4; j++) pb[j] = *(const float4*)(bp + j * 4);
        }
        {
            const uint32_t* a = (const uint32_t*)(As + s * A_SZ);
            const uint32_t* b = (const uint32_t*)(Bs + s * B128_SZ);
            #pragma unroll
            for (int kb = 0; kb < 32; kb += 8) {
                uint32_t af[2][4];
                #pragma unroll
                for (int mi = 0; mi < 2; mi++) {
                    int r = wm * 32 + mi * 16 + gid;
                    af[mi][0] = a[r * SA + kb + t4];
                    af[mi][1] = a[(r + 8) * SA + kb + t4];
                    af[mi][2] = a[r * SA + kb + t4 + 4];
                    af[mi][3] = a[(r + 8) * SA + kb + t4 + 4];
                }
                #pragma unroll
                for (int ni = 0; ni < 8; ni++) {
                    int n = wn * 64 + ni * 8 + gid;
                    uint32_t bf[2] = {b[n * SA + kb + t4], b[n * SA + kb + t4 + 4]};
                    #pragma unroll
                    for (int mi = 0; mi < 2; mi++) mma8(acc[mi][ni], af[mi], bf);
                }
            }
        }
        __syncthreads();
    }

    // ---- epilogue: weighted atomic accumulate
    #pragma unroll
    for (int mi = 0; mi < 2; mi++) {
        int rb = row0 + wm * 32 + mi * 16 + gid;
        #pragma unroll
        for (int h = 0; h < 2; h++) {
            int r = rb + h * 8;
            if (r < cnt) {
                int   t = (z == 0) ? r : g_tok[e * T_ + r];
                float w = (z == 0) ? 1.f : g_wt[e * T_ + r];
                float* op = out + (size_t)t * H_ + col0 + wn * 64;
                #pragma unroll
                for (int ni = 0; ni < 8; ni++) {
                    int c = ni * 8 + t4 * 2;
                    atomicAdd(op + c,     w * acc[mi][ni][h * 2 + 0]);
                    atomicAdd(op + c + 1, w * acc[mi][ni][h * 2 + 1]);
                }
            }
        }
    }
}

// ---------------- launch ----------------
#define G1_SMEM ((2 * A_SZ + 4 * B64_SZ) * 4 + 512)
#define G2_SMEM ((2 * A_SZ + 2 * B128_SZ) * 4)

extern "C" void kernel_launch(void* const* d_in, const int* in_sizes, int n_in,
                              void* d_out, int out_size) {
    const float* x   = (const float*)d_in[0];
    const float* rw  = (const float*)d_in[1];
    const float* wg  = (const float*)d_in[2];
    const float* wu  = (const float*)d_in[3];
    const float* wd  = (const float*)d_in[4];
    const float* wgu = (const float*)d_in[5];
    const float* wsd = (const float*)d_in[6];
    float* out = (float*)d_out;

    cudaFuncSetAttribute(gemm1_mma, cudaFuncAttributeMaxDynamicSharedMemorySize, G1_SMEM);
    cudaFuncSetAttribute(gemm2_mma, cudaFuncAttributeMaxDynamicSharedMemorySize, G2_SMEM);

    cudaMemsetAsync(d_out, 0, (size_t)out_size * sizeof(float), 0);
    zero_counts_kernel<<<1, 32>>>();
    router_kernel<<<T_, 256>>>(x, rw);
    // z=0 = shared expert (largest K) scheduled first
    gemm1_mma<<<dim3(IS_ / 64, T_ / 128, E_ + 1), 256, G1_SMEM>>>(x, wg, wu, wgu);
    gemm2_mma<<<dim3(H_ / 128, T_ / 128, E_ + 1), 256, G2_SMEM>>>(wd, wsd, out);
}